// round 1
// baseline (speedup 1.0000x reference)
#include <cuda_runtime.h>
#include <math.h>

#define S_LEN   4096
#define D_MODEL 768
#define NH      12
#define DHEAD   64
#define BATCH   2
#define ROWS    (BATCH * S_LEN)   // 8192

// Scratch (allocation-free rule: __device__ globals)
__device__ float g_q[ROWS * D_MODEL];
__device__ float g_k[ROWS * D_MODEL];
__device__ float g_v[ROWS * D_MODEL];
__device__ float g_att[ROWS * D_MODEL];

// ---------------------------------------------------------------------------
// C[M,N] = A[M,K] @ W[N,K]^T + bias[N]
// 64x64 block tile, BK=16, 256 threads, 4x4 microtile per thread.
// ---------------------------------------------------------------------------
__global__ void __launch_bounds__(256) gemm_nt_bias(
    const float* __restrict__ A, const float* __restrict__ W,
    const float* __restrict__ bias, float* __restrict__ C,
    int M, int N, int K)
{
    __shared__ float As[16 * 64];  // [k][m]
    __shared__ float Bs[16 * 64];  // [k][n]

    const int t  = threadIdx.x;
    const int tx = t & 15;
    const int ty = t >> 4;
    const int m0 = blockIdx.y * 64;
    const int n0 = blockIdx.x * 64;

    const int lrow = t >> 2;   // 0..63
    const int kq   = t & 3;    // 0..3 (float4 quad within the 16-wide k tile)

    const float* Aptr = A + (size_t)(m0 + lrow) * K + kq * 4;
    const float* Wptr = W + (size_t)(n0 + lrow) * K + kq * 4;

    float acc[4][4] = {};

    for (int k0 = 0; k0 < K; k0 += 16) {
        float4 a4 = *(const float4*)(Aptr + k0);
        float4 w4 = *(const float4*)(Wptr + k0);
        As[(4 * kq + 0) * 64 + lrow] = a4.x;
        As[(4 * kq + 1) * 64 + lrow] = a4.y;
        As[(4 * kq + 2) * 64 + lrow] = a4.z;
        As[(4 * kq + 3) * 64 + lrow] = a4.w;
        Bs[(4 * kq + 0) * 64 + lrow] = w4.x;
        Bs[(4 * kq + 1) * 64 + lrow] = w4.y;
        Bs[(4 * kq + 2) * 64 + lrow] = w4.z;
        Bs[(4 * kq + 3) * 64 + lrow] = w4.w;
        __syncthreads();

#pragma unroll
        for (int kk = 0; kk < 16; kk++) {
            float ar[4], wc[4];
#pragma unroll
            for (int r = 0; r < 4; r++) ar[r] = As[kk * 64 + ty + 16 * r];
#pragma unroll
            for (int c = 0; c < 4; c++) wc[c] = Bs[kk * 64 + tx + 16 * c];
#pragma unroll
            for (int r = 0; r < 4; r++)
#pragma unroll
                for (int c = 0; c < 4; c++)
                    acc[r][c] += ar[r] * wc[c];
        }
        __syncthreads();
    }

#pragma unroll
    for (int r = 0; r < 4; r++) {
        const int m = m0 + ty + 16 * r;
#pragma unroll
        for (int c = 0; c < 4; c++) {
            const int n = n0 + tx + 16 * c;
            C[(size_t)m * N + n] = acc[r][c] + bias[n];
        }
    }
}

// ---------------------------------------------------------------------------
// Flash-attention style streaming kernel.
// Grid: (S/64, B*H). Block: 256 threads (16x16), each owns 4x4 of a 64x64 tile.
// Q/K/V/att laid out as [B*S][H*DH] row-major (from the projection GEMMs).
// Dynamic smem: Qs 64x64 | Ks 64x65 (reused as P) | Vs 64x64 | msk[64]
// ---------------------------------------------------------------------------
__global__ void __launch_bounds__(256) attn_kernel(
    const float* __restrict__ Qg, const float* __restrict__ Kg,
    const float* __restrict__ Vg, const int* __restrict__ mask,
    float* __restrict__ Og)
{
    extern __shared__ float sm[];
    float* Qs = sm;                 // 4096 floats, stride 64
    float* Ks = sm + 4096;          // 4160 floats, stride 65 (also holds P)
    float* Vs = sm + 4096 + 4160;   // 4096 floats, stride 64
    int*   msk = (int*)(sm + 12352);

    const int t  = threadIdx.x;
    const int tx = t & 15;
    const int ty = t >> 4;
    const int qb = blockIdx.x;
    const int bh = blockIdx.y;
    const int b  = bh / NH;
    const int hh = bh % NH;

    const int qrow0 = b * S_LEN + qb * 64;
    const int hcol  = hh * DHEAD;

    // Load Q tile (64x64), stride-64 smem, float4.
#pragma unroll
    for (int i = 0; i < 4; i++) {
        int idx = t + 256 * i;
        int lr  = idx >> 4;
        int c4  = idx & 15;
        float4 v = *(const float4*)&Qg[(size_t)(qrow0 + lr) * D_MODEL + hcol + c4 * 4];
        *(float4*)&Qs[lr * 64 + c4 * 4] = v;
    }

    float o[4][4] = {};
    float mrow[4], lrow[4];
#pragma unroll
    for (int r = 0; r < 4; r++) { mrow[r] = -INFINITY; lrow[r] = 0.f; }

    for (int jb = 0; jb < S_LEN / 64; jb++) {
        __syncthreads();  // previous PV done (also orders Q load on jb==0)

        const int krow0 = b * S_LEN + jb * 64;
        // Load K (stride-65, scalar stores: rows not 16B aligned) and V (float4)
#pragma unroll
        for (int i = 0; i < 4; i++) {
            int idx = t + 256 * i;
            int lr  = idx >> 4;
            int c4  = idx & 15;
            float4 kv = *(const float4*)&Kg[(size_t)(krow0 + lr) * D_MODEL + hcol + c4 * 4];
            Ks[lr * 65 + c4 * 4 + 0] = kv.x;
            Ks[lr * 65 + c4 * 4 + 1] = kv.y;
            Ks[lr * 65 + c4 * 4 + 2] = kv.z;
            Ks[lr * 65 + c4 * 4 + 3] = kv.w;
            float4 vv = *(const float4*)&Vg[(size_t)(krow0 + lr) * D_MODEL + hcol + c4 * 4];
            *(float4*)&Vs[lr * 64 + c4 * 4] = vv;
        }
        if (t < 64) msk[t] = mask[b * S_LEN + jb * 64 + t];
        __syncthreads();

        // Scores: s[r][c] = sum_d Q[qr][d] * K[kc][d]
        float s[4][4] = {};
#pragma unroll 8
        for (int d = 0; d < 64; d++) {
            float qv[4], kv[4];
#pragma unroll
            for (int r = 0; r < 4; r++) qv[r] = Qs[(ty + 16 * r) * 64 + d];
#pragma unroll
            for (int c = 0; c < 4; c++) kv[c] = Ks[(tx + 16 * c) * 65 + d];
#pragma unroll
            for (int r = 0; r < 4; r++)
#pragma unroll
                for (int c = 0; c < 4; c++)
                    s[r][c] += qv[r] * kv[c];
        }

        // Scale + mask + online softmax update
        float corr[4];
#pragma unroll
        for (int r = 0; r < 4; r++) {
            float mx = -INFINITY;
#pragma unroll
            for (int c = 0; c < 4; c++) {
                float sv = msk[tx + 16 * c] ? -1e9f : s[r][c] * 0.125f;
                s[r][c] = sv;
                mx = fmaxf(mx, sv);
            }
#pragma unroll
            for (int off = 8; off > 0; off >>= 1)
                mx = fmaxf(mx, __shfl_xor_sync(0xffffffffu, mx, off));
            float mnew = fmaxf(mrow[r], mx);
            corr[r] = __expf(mrow[r] - mnew);
            mrow[r] = mnew;
            float rs = 0.f;
#pragma unroll
            for (int c = 0; c < 4; c++) {
                float p = __expf(s[r][c] - mnew);
                s[r][c] = p;
                rs += p;
            }
#pragma unroll
            for (int off = 8; off > 0; off >>= 1)
                rs += __shfl_xor_sync(0xffffffffu, rs, off);
            lrow[r] = lrow[r] * corr[r] + rs;
#pragma unroll
            for (int c = 0; c < 4; c++) o[r][c] *= corr[r];
        }

        __syncthreads();  // everyone done reading Ks before it becomes P
#pragma unroll
        for (int r = 0; r < 4; r++)
#pragma unroll
            for (int c = 0; c < 4; c++)
                Ks[(ty + 16 * r) * 65 + tx + 16 * c] = s[r][c];
        __syncthreads();

        // O += P @ V
#pragma unroll 8
        for (int k = 0; k < 64; k++) {
            float pv[4], vv[4];
#pragma unroll
            for (int r = 0; r < 4; r++) pv[r] = Ks[(ty + 16 * r) * 65 + k];
#pragma unroll
            for (int c = 0; c < 4; c++) vv[c] = Vs[k * 64 + tx + 16 * c];
#pragma unroll
            for (int r = 0; r < 4; r++)
#pragma unroll
                for (int c = 0; c < 4; c++)
                    o[r][c] += pv[r] * vv[c];
        }
    }

    // Normalize + write att [B*S][H*DH]
#pragma unroll
    for (int r = 0; r < 4; r++) {
        float inv = 1.f / lrow[r];
        const int m = qrow0 + ty + 16 * r;
#pragma unroll
        for (int c = 0; c < 4; c++)
            Og[(size_t)m * D_MODEL + hcol + tx + 16 * c] = o[r][c] * inv;
    }
}

// ---------------------------------------------------------------------------
extern "C" void kernel_launch(void* const* d_in, const int* in_sizes, int n_in,
                              void* d_out, int out_size)
{
    const float* h   = (const float*)d_in[0];
    const float* Wq  = (const float*)d_in[1];
    const float* bq  = (const float*)d_in[2];
    const float* Wk  = (const float*)d_in[3];
    const float* bk  = (const float*)d_in[4];
    const float* Wv  = (const float*)d_in[5];
    const float* bv  = (const float*)d_in[6];
    const float* Wo  = (const float*)d_in[7];
    const float* bo  = (const float*)d_in[8];
    const int*   msk = (const int*)d_in[9];
    float* out = (float*)d_out;

    void *pq, *pk, *pv, *pa;
    cudaGetSymbolAddress(&pq, g_q);
    cudaGetSymbolAddress(&pk, g_k);
    cudaGetSymbolAddress(&pv, g_v);
    cudaGetSymbolAddress(&pa, g_att);

    const int smem_bytes = (12352 * 4) + (64 * 4);  // 49664
    cudaFuncSetAttribute(attn_kernel, cudaFuncAttributeMaxDynamicSharedMemorySize,
                         smem_bytes);

    dim3 gthr(256);
    dim3 ggrid(D_MODEL / 64, ROWS / 64);  // (12, 128)

    gemm_nt_bias<<<ggrid, gthr>>>(h, Wq, bq, (float*)pq, ROWS, D_MODEL, D_MODEL);
    gemm_nt_bias<<<ggrid, gthr>>>(h, Wk, bk, (float*)pk, ROWS, D_MODEL, D_MODEL);
    gemm_nt_bias<<<ggrid, gthr>>>(h, Wv, bv, (float*)pv, ROWS, D_MODEL, D_MODEL);

    dim3 agrid(S_LEN / 64, BATCH * NH);   // (64, 24)
    attn_kernel<<<agrid, gthr, smem_bytes>>>((const float*)pq, (const float*)pk,
                                             (const float*)pv, msk, (float*)pa);

    gemm_nt_bias<<<ggrid, gthr>>>((const float*)pa, Wo, bo, out, ROWS, D_MODEL, D_MODEL);
}

// round 2
// speedup vs baseline: 3.2222x; 3.2222x over previous
#include <cuda_runtime.h>
#include <math.h>

#define S_LEN   4096
#define D_MODEL 768
#define NH      12
#define DHEAD   64
#define BATCH   2
#define ROWS    (BATCH * S_LEN)   // 8192

// Scratch (allocation-free rule: __device__ globals)
__device__ float g_q[ROWS * D_MODEL];
__device__ float g_k[ROWS * D_MODEL];
__device__ float g_v[ROWS * D_MODEL];
__device__ float g_att[ROWS * D_MODEL];

// ---------------------------------------------------------------------------
// tf32 helpers
// ---------------------------------------------------------------------------
__device__ __forceinline__ unsigned f2tf(float f) {
    unsigned u;
    asm("cvt.rna.tf32.f32 %0, %1;" : "=r"(u) : "f"(f));
    return u;
}

__device__ __forceinline__ void mma_tf32(float c[4],
                                         unsigned a0, unsigned a1, unsigned a2, unsigned a3,
                                         unsigned b0, unsigned b1) {
    asm volatile(
        "mma.sync.aligned.m16n8k8.row.col.f32.tf32.tf32.f32 "
        "{%0,%1,%2,%3}, {%4,%5,%6,%7}, {%8,%9}, {%0,%1,%2,%3};"
        : "+f"(c[0]), "+f"(c[1]), "+f"(c[2]), "+f"(c[3])
        : "r"(a0), "r"(a1), "r"(a2), "r"(a3), "r"(b0), "r"(b1));
}

// ---------------------------------------------------------------------------
// C[M,N] = A[M,K] @ W[N,K]^T + bias   (tf32 tensor cores)
// Block tile 128x64, BK=16, 256 threads (8 warps), warp tile 16x64.
// smem stride 20: fragment loads (g*20 + tig) mod 32 hit all 32 banks.
// ---------------------------------------------------------------------------
#define GST 20

__global__ void __launch_bounds__(256) gemm_tf32(
    const float* __restrict__ A, const float* __restrict__ W,
    const float* __restrict__ bias, float* __restrict__ C,
    int M, int N, int K)
{
    __shared__ unsigned As[128 * GST];
    __shared__ unsigned Bs[64 * GST];

    const int t    = threadIdx.x;
    const int warp = t >> 5;
    const int lane = t & 31;
    const int g    = lane >> 2;
    const int tig  = lane & 3;
    const int m0   = blockIdx.y * 128;
    const int n0   = blockIdx.x * 64;

    // Global load mapping: A 128x16 floats (512 f4, 2/thread), B 64x16 (256 f4, 1/thread)
    const int arow0 = t >> 2;          // 0..63
    const int ac4   = t & 3;
    const float* Ap0 = A + (size_t)(m0 + arow0) * K + ac4 * 4;
    const float* Ap1 = A + (size_t)(m0 + arow0 + 64) * K + ac4 * 4;
    const float* Wp  = W + (size_t)(n0 + arow0) * K + ac4 * 4;

    float acc[8][4] = {};

    float4 ra0 = *(const float4*)(Ap0);
    float4 ra1 = *(const float4*)(Ap1);
    float4 rb  = *(const float4*)(Wp);

    for (int k0 = 0; k0 < K; k0 += 16) {
        // stage to smem (cvt to tf32)
        {
            uint4 u;
            u.x = f2tf(ra0.x); u.y = f2tf(ra0.y); u.z = f2tf(ra0.z); u.w = f2tf(ra0.w);
            *(uint4*)&As[arow0 * GST + ac4 * 4] = u;
            u.x = f2tf(ra1.x); u.y = f2tf(ra1.y); u.z = f2tf(ra1.z); u.w = f2tf(ra1.w);
            *(uint4*)&As[(arow0 + 64) * GST + ac4 * 4] = u;
            u.x = f2tf(rb.x); u.y = f2tf(rb.y); u.z = f2tf(rb.z); u.w = f2tf(rb.w);
            *(uint4*)&Bs[arow0 * GST + ac4 * 4] = u;
        }
        __syncthreads();

        if (k0 + 16 < K) {
            ra0 = *(const float4*)(Ap0 + k0 + 16);
            ra1 = *(const float4*)(Ap1 + k0 + 16);
            rb  = *(const float4*)(Wp + k0 + 16);
        }

#pragma unroll
        for (int ks = 0; ks < 2; ks++) {
            const int kc = ks * 8 + tig;
            unsigned a0 = As[(warp * 16 + g) * GST + kc];
            unsigned a1 = As[(warp * 16 + g + 8) * GST + kc];
            unsigned a2 = As[(warp * 16 + g) * GST + kc + 4];
            unsigned a3 = As[(warp * 16 + g + 8) * GST + kc + 4];
#pragma unroll
            for (int nt = 0; nt < 8; nt++) {
                unsigned b0 = Bs[(nt * 8 + g) * GST + kc];
                unsigned b1 = Bs[(nt * 8 + g) * GST + kc + 4];
                mma_tf32(acc[nt], a0, a1, a2, a3, b0, b1);
            }
        }
        __syncthreads();
    }

    // Epilogue: c0,c1 -> (row g, cols 2tig,2tig+1); c2,c3 -> row g+8
    const int row0 = m0 + warp * 16 + g;
#pragma unroll
    for (int nt = 0; nt < 8; nt++) {
        const int col = n0 + nt * 8 + 2 * tig;
        const float b0v = bias[col], b1v = bias[col + 1];
        *(float2*)&C[(size_t)row0 * N + col] =
            make_float2(acc[nt][0] + b0v, acc[nt][1] + b1v);
        *(float2*)&C[(size_t)(row0 + 8) * N + col] =
            make_float2(acc[nt][2] + b0v, acc[nt][3] + b1v);
    }
}

// ---------------------------------------------------------------------------
// Flash attention with tf32 tensor cores.
// Grid: (S/128, B*H). Block 256 threads (8 warps); warp w owns q-rows [16w,16w+16).
// smem (tf32 bits): Qs[128][68] | Ks[64][68] | Vs[64][72] | Ps[128][68] | msk[64]
// Strides: 68 -> frag loads (g*4+tig) conflict-free; 72 -> V B-frag (tig*8+g) conflict-free.
// ---------------------------------------------------------------------------
#define QST 68
#define KST 68
#define VST 72
#define PST 68

__global__ void __launch_bounds__(256, 2) attn_tc(
    const float* __restrict__ Qg, const float* __restrict__ Kg,
    const float* __restrict__ Vg, const int* __restrict__ mask,
    float* __restrict__ Og)
{
    extern __shared__ unsigned sm[];
    unsigned* Qs = sm;                       // 128*68
    unsigned* Ks = Qs + 128 * QST;           // 64*68
    unsigned* Vs = Ks + 64 * KST;            // 64*72
    unsigned* Ps = Vs + 64 * VST;            // 128*68
    int* msk = (int*)(Ps + 128 * PST);       // 64

    const int t    = threadIdx.x;
    const int warp = t >> 5;
    const int lane = t & 31;
    const int g    = lane >> 2;
    const int tig  = lane & 3;

    const int qb = blockIdx.x;
    const int bh = blockIdx.y;
    const int b  = bh / NH;
    const int hh = bh % NH;
    const int qrow0 = b * S_LEN + qb * 128;
    const int hcol  = hh * DHEAD;

    // Load Q tile 128x64 (coalesced f4, cvt to tf32)
    {
        const int row = t >> 4;     // 0..15 per pass
        const int c4  = t & 15;
#pragma unroll
        for (int i = 0; i < 8; i++) {
            const int r = row + i * 16;
            float4 v = *(const float4*)&Qg[(size_t)(qrow0 + r) * D_MODEL + hcol + c4 * 4];
            uint4 u;
            u.x = f2tf(v.x); u.y = f2tf(v.y); u.z = f2tf(v.z); u.w = f2tf(v.w);
            *(uint4*)&Qs[r * QST + c4 * 4] = u;
        }
    }

    float o[8][4] = {};
    float mr0 = -INFINITY, mr1 = -INFINITY;
    float l0 = 0.f, l1 = 0.f;

    const int prow0 = warp * 16 + g;
    const int prow1 = warp * 16 + g + 8;

    for (int jb = 0; jb < S_LEN / 64; jb++) {
        __syncthreads();  // previous iter done with Ks/Vs (also orders Q on jb==0)

        const int krow0 = b * S_LEN + jb * 64;
        {
            const int row = t >> 4;
            const int c4  = t & 15;
#pragma unroll
            for (int i = 0; i < 4; i++) {
                const int r = row + i * 16;
                float4 kv = *(const float4*)&Kg[(size_t)(krow0 + r) * D_MODEL + hcol + c4 * 4];
                uint4 u;
                u.x = f2tf(kv.x); u.y = f2tf(kv.y); u.z = f2tf(kv.z); u.w = f2tf(kv.w);
                *(uint4*)&Ks[r * KST + c4 * 4] = u;
                float4 vv = *(const float4*)&Vg[(size_t)(krow0 + r) * D_MODEL + hcol + c4 * 4];
                u.x = f2tf(vv.x); u.y = f2tf(vv.y); u.z = f2tf(vv.z); u.w = f2tf(vv.w);
                *(uint4*)&Vs[r * VST + c4 * 4] = u;
            }
        }
        if (t < 64) msk[t] = mask[b * S_LEN + jb * 64 + t];
        __syncthreads();

        // ---- S = Q @ K^T  (warp: 16 q-rows x 64 k-cols) ----
        float s[8][4] = {};
#pragma unroll
        for (int ks = 0; ks < 8; ks++) {
            const int kc = ks * 8 + tig;
            unsigned a0 = Qs[prow0 * QST + kc];
            unsigned a1 = Qs[prow1 * QST + kc];
            unsigned a2 = Qs[prow0 * QST + kc + 4];
            unsigned a3 = Qs[prow1 * QST + kc + 4];
#pragma unroll
            for (int nt = 0; nt < 8; nt++) {
                unsigned b0 = Ks[(nt * 8 + g) * KST + kc];
                unsigned b1 = Ks[(nt * 8 + g) * KST + kc + 4];
                mma_tf32(s[nt], a0, a1, a2, a3, b0, b1);
            }
        }

        // ---- scale + mask + online softmax (rows g / g+8 of this warp) ----
        float mx0 = -INFINITY, mx1 = -INFINITY;
#pragma unroll
        for (int nt = 0; nt < 8; nt++) {
#pragma unroll
            for (int j = 0; j < 2; j++) {
                const int mk = msk[nt * 8 + 2 * tig + j];
                float v0 = mk ? -1e9f : s[nt][j] * 0.125f;
                float v1 = mk ? -1e9f : s[nt][2 + j] * 0.125f;
                s[nt][j] = v0; s[nt][2 + j] = v1;
                mx0 = fmaxf(mx0, v0); mx1 = fmaxf(mx1, v1);
            }
        }
        mx0 = fmaxf(mx0, __shfl_xor_sync(0xffffffffu, mx0, 1));
        mx0 = fmaxf(mx0, __shfl_xor_sync(0xffffffffu, mx0, 2));
        mx1 = fmaxf(mx1, __shfl_xor_sync(0xffffffffu, mx1, 1));
        mx1 = fmaxf(mx1, __shfl_xor_sync(0xffffffffu, mx1, 2));

        const float mn0 = fmaxf(mr0, mx0);
        const float mn1 = fmaxf(mr1, mx1);
        const float corr0 = __expf(mr0 - mn0);
        const float corr1 = __expf(mr1 - mn1);
        mr0 = mn0; mr1 = mn1;

        float rs0 = 0.f, rs1 = 0.f;
#pragma unroll
        for (int nt = 0; nt < 8; nt++) {
#pragma unroll
            for (int j = 0; j < 2; j++) {
                float p0 = __expf(s[nt][j] - mn0);
                float p1 = __expf(s[nt][2 + j] - mn1);
                s[nt][j] = p0; s[nt][2 + j] = p1;
                rs0 += p0; rs1 += p1;
            }
        }
        rs0 += __shfl_xor_sync(0xffffffffu, rs0, 1);
        rs0 += __shfl_xor_sync(0xffffffffu, rs0, 2);
        rs1 += __shfl_xor_sync(0xffffffffu, rs1, 1);
        rs1 += __shfl_xor_sync(0xffffffffu, rs1, 2);
        l0 = l0 * corr0 + rs0;
        l1 = l1 * corr1 + rs1;

#pragma unroll
        for (int nt = 0; nt < 8; nt++) {
            o[nt][0] *= corr0; o[nt][1] *= corr0;
            o[nt][2] *= corr1; o[nt][3] *= corr1;
        }

        // ---- stage P (warp-private rows) ----
#pragma unroll
        for (int nt = 0; nt < 8; nt++) {
            const int col = nt * 8 + 2 * tig;
            Ps[prow0 * PST + col]     = f2tf(s[nt][0]);
            Ps[prow0 * PST + col + 1] = f2tf(s[nt][1]);
            Ps[prow1 * PST + col]     = f2tf(s[nt][2]);
            Ps[prow1 * PST + col + 1] = f2tf(s[nt][3]);
        }
        __syncwarp();

        // ---- O += P @ V  (k = 64 keys, n = 64 dh) ----
#pragma unroll
        for (int ks = 0; ks < 8; ks++) {
            const int kc = ks * 8 + tig;
            unsigned a0 = Ps[prow0 * PST + kc];
            unsigned a1 = Ps[prow1 * PST + kc];
            unsigned a2 = Ps[prow0 * PST + kc + 4];
            unsigned a3 = Ps[prow1 * PST + kc + 4];
#pragma unroll
            for (int nt = 0; nt < 8; nt++) {
                unsigned b0 = Vs[(ks * 8 + tig) * VST + nt * 8 + g];
                unsigned b1 = Vs[(ks * 8 + tig + 4) * VST + nt * 8 + g];
                mma_tf32(o[nt], a0, a1, a2, a3, b0, b1);
            }
        }
        __syncwarp();  // P reads done before next iter's softmax rewrites it
    }

    // ---- normalize + write ----
    const float inv0 = 1.f / l0;
    const float inv1 = 1.f / l1;
    const int row0 = qrow0 + warp * 16 + g;
#pragma unroll
    for (int nt = 0; nt < 8; nt++) {
        const int col = hcol + nt * 8 + 2 * tig;
        *(float2*)&Og[(size_t)row0 * D_MODEL + col] =
            make_float2(o[nt][0] * inv0, o[nt][1] * inv0);
        *(float2*)&Og[(size_t)(row0 + 8) * D_MODEL + col] =
            make_float2(o[nt][2] * inv1, o[nt][3] * inv1);
    }
}

// ---------------------------------------------------------------------------
extern "C" void kernel_launch(void* const* d_in, const int* in_sizes, int n_in,
                              void* d_out, int out_size)
{
    const float* h   = (const float*)d_in[0];
    const float* Wq  = (const float*)d_in[1];
    const float* bq  = (const float*)d_in[2];
    const float* Wk  = (const float*)d_in[3];
    const float* bk  = (const float*)d_in[4];
    const float* Wv  = (const float*)d_in[5];
    const float* bv  = (const float*)d_in[6];
    const float* Wo  = (const float*)d_in[7];
    const float* bo  = (const float*)d_in[8];
    const int*   msk = (const int*)d_in[9];
    float* out = (float*)d_out;

    void *pq, *pk, *pv, *pa;
    cudaGetSymbolAddress(&pq, g_q);
    cudaGetSymbolAddress(&pk, g_k);
    cudaGetSymbolAddress(&pv, g_v);
    cudaGetSymbolAddress(&pa, g_att);

    const int attn_smem = (128 * QST + 64 * KST + 64 * VST + 128 * PST) * 4 + 64 * 4;
    cudaFuncSetAttribute(attn_tc, cudaFuncAttributeMaxDynamicSharedMemorySize,
                         attn_smem);

    dim3 gthr(256);
    dim3 ggrid(D_MODEL / 64, ROWS / 128);   // (12, 64)

    gemm_tf32<<<ggrid, gthr>>>(h, Wq, bq, (float*)pq, ROWS, D_MODEL, D_MODEL);
    gemm_tf32<<<ggrid, gthr>>>(h, Wk, bk, (float*)pk, ROWS, D_MODEL, D_MODEL);
    gemm_tf32<<<ggrid, gthr>>>(h, Wv, bv, (float*)pv, ROWS, D_MODEL, D_MODEL);

    dim3 agrid(S_LEN / 128, BATCH * NH);    // (32, 24)
    attn_tc<<<agrid, gthr, attn_smem>>>((const float*)pq, (const float*)pk,
                                        (const float*)pv, msk, (float*)pa);

    gemm_tf32<<<ggrid, gthr>>>((const float*)pa, Wo, bo, out, ROWS, D_MODEL, D_MODEL);
}

// round 3
// speedup vs baseline: 3.6627x; 1.1367x over previous
#include <cuda_runtime.h>
#include <math.h>

#define S_LEN   4096
#define D_MODEL 768
#define NH      12
#define DHEAD   64
#define BATCH   2
#define ROWS    (BATCH * S_LEN)   // 8192

// Scratch (allocation-free rule: __device__ globals)
__device__ float g_q[ROWS * D_MODEL];
__device__ float g_k[ROWS * D_MODEL];
__device__ float g_v[ROWS * D_MODEL];
__device__ float g_att[ROWS * D_MODEL];

// ---------------------------------------------------------------------------
// tf32 helpers
// ---------------------------------------------------------------------------
__device__ __forceinline__ unsigned f2tf(float f) {
    unsigned u;
    asm("cvt.rna.tf32.f32 %0, %1;" : "=r"(u) : "f"(f));
    return u;
}

__device__ __forceinline__ void mma_tf32(float c[4],
                                         const unsigned a[4],
                                         unsigned b0, unsigned b1) {
    asm volatile(
        "mma.sync.aligned.m16n8k8.row.col.f32.tf32.tf32.f32 "
        "{%0,%1,%2,%3}, {%4,%5,%6,%7}, {%8,%9}, {%0,%1,%2,%3};"
        : "+f"(c[0]), "+f"(c[1]), "+f"(c[2]), "+f"(c[3])
        : "r"(a[0]), "r"(a[1]), "r"(a[2]), "r"(a[3]), "r"(b0), "r"(b1));
}

// ---------------------------------------------------------------------------
// C[M,N] = A[M,K] @ W[N,K]^T + bias   (tf32 tensor cores)
// Block tile 128x64, BK=16, 128 threads (4 warps), warp tile 32x64.
// Double-buffered smem -> single __syncthreads per k-tile.
// smem stride 20: fragment loads (g*20 + tig) mod 32 hit all 32 banks.
// ---------------------------------------------------------------------------
#define GST 20

__global__ void __launch_bounds__(128) gemm_tf32(
    const float* __restrict__ A, const float* __restrict__ W,
    const float* __restrict__ bias, float* __restrict__ C,
    int M, int N, int K)
{
    __shared__ unsigned As[2][128 * GST];
    __shared__ unsigned Bs[2][64 * GST];

    const int t    = threadIdx.x;
    const int warp = t >> 5;
    const int lane = t & 31;
    const int g    = lane >> 2;
    const int tig  = lane & 3;
    const int m0   = blockIdx.y * 128;
    const int n0   = blockIdx.x * 64;

    // Global load mapping: A 128x16 floats (512 f4 -> 4/thread), B 64x16 (2/thread)
    const int arow = t >> 2;           // 0..31
    const int ac4  = t & 3;
    const float* Ap = A + (size_t)(m0 + arow) * K + ac4 * 4;
    const float* Wp = W + (size_t)(n0 + arow) * K + ac4 * 4;

    float acc[2][8][4] = {};

    float4 ra[4], rb[2];
#pragma unroll
    for (int i = 0; i < 4; i++) ra[i] = *(const float4*)(Ap + (size_t)(32 * i) * K);
#pragma unroll
    for (int i = 0; i < 2; i++) rb[i] = *(const float4*)(Wp + (size_t)(32 * i) * K);

    int buf = 0;
    for (int k0 = 0; k0 < K; k0 += 16) {
        // stage to smem (cvt to tf32)
#pragma unroll
        for (int i = 0; i < 4; i++) {
            uint4 u;
            u.x = f2tf(ra[i].x); u.y = f2tf(ra[i].y);
            u.z = f2tf(ra[i].z); u.w = f2tf(ra[i].w);
            *(uint4*)&As[buf][(arow + 32 * i) * GST + ac4 * 4] = u;
        }
#pragma unroll
        for (int i = 0; i < 2; i++) {
            uint4 u;
            u.x = f2tf(rb[i].x); u.y = f2tf(rb[i].y);
            u.z = f2tf(rb[i].z); u.w = f2tf(rb[i].w);
            *(uint4*)&Bs[buf][(arow + 32 * i) * GST + ac4 * 4] = u;
        }
        __syncthreads();

        if (k0 + 16 < K) {
#pragma unroll
            for (int i = 0; i < 4; i++)
                ra[i] = *(const float4*)(Ap + (size_t)(32 * i) * K + k0 + 16);
#pragma unroll
            for (int i = 0; i < 2; i++)
                rb[i] = *(const float4*)(Wp + (size_t)(32 * i) * K + k0 + 16);
        }

#pragma unroll
        for (int ks = 0; ks < 2; ks++) {
            const int kc = ks * 8 + tig;
            unsigned a[2][4];
#pragma unroll
            for (int ti = 0; ti < 2; ti++) {
                const int r = warp * 32 + ti * 16 + g;
                a[ti][0] = As[buf][r * GST + kc];
                a[ti][1] = As[buf][(r + 8) * GST + kc];
                a[ti][2] = As[buf][r * GST + kc + 4];
                a[ti][3] = As[buf][(r + 8) * GST + kc + 4];
            }
#pragma unroll
            for (int nt = 0; nt < 8; nt++) {
                unsigned b0 = Bs[buf][(nt * 8 + g) * GST + kc];
                unsigned b1 = Bs[buf][(nt * 8 + g) * GST + kc + 4];
                mma_tf32(acc[0][nt], a[0], b0, b1);
                mma_tf32(acc[1][nt], a[1], b0, b1);
            }
        }
        buf ^= 1;   // next stores go to the other buffer; no second sync needed
    }

#pragma unroll
    for (int ti = 0; ti < 2; ti++) {
        const int row0 = m0 + warp * 32 + ti * 16 + g;
#pragma unroll
        for (int nt = 0; nt < 8; nt++) {
            const int col = n0 + nt * 8 + 2 * tig;
            const float b0v = bias[col], b1v = bias[col + 1];
            *(float2*)&C[(size_t)row0 * N + col] =
                make_float2(acc[ti][nt][0] + b0v, acc[ti][nt][1] + b1v);
            *(float2*)&C[(size_t)(row0 + 8) * N + col] =
                make_float2(acc[ti][nt][2] + b0v, acc[ti][nt][3] + b1v);
        }
    }
}

// ---------------------------------------------------------------------------
// Flash attention, tf32 tensor cores, 32-row warp tiles.
// Grid: (S/128, B*H). Block 128 threads (4 warps); warp w owns q-rows [32w,32w+32).
// smem (tf32 bits): Qs[128][68] | Ks[64][68] | Vs[64][72] | Ps[128][68] | msk[64]
// ---------------------------------------------------------------------------
#define QST 68
#define KST 68
#define VST 72
#define PST 68

__global__ void __launch_bounds__(128) attn_tc(
    const float* __restrict__ Qg, const float* __restrict__ Kg,
    const float* __restrict__ Vg, const int* __restrict__ mask,
    float* __restrict__ Og)
{
    extern __shared__ unsigned sm[];
    unsigned* Qs = sm;                       // 128*68
    unsigned* Ks = Qs + 128 * QST;           // 64*68
    unsigned* Vs = Ks + 64 * KST;            // 64*72
    unsigned* Ps = Vs + 64 * VST;            // 128*68
    int* msk = (int*)(Ps + 128 * PST);       // 64

    const int t    = threadIdx.x;
    const int warp = t >> 5;
    const int lane = t & 31;
    const int g    = lane >> 2;
    const int tig  = lane & 3;

    const int qb = blockIdx.x;
    const int bh = blockIdx.y;
    const int b  = bh / NH;
    const int hh = bh % NH;
    const int qrow0 = b * S_LEN + qb * 128;
    const int hcol  = hh * DHEAD;

    const int R0 = warp * 32;
    const int pr0 = R0 + g;          // m16-tile 0 base row
    const int pr1 = R0 + 16 + g;     // m16-tile 1 base row

    // Load Q tile 128x64 (coalesced f4, cvt to tf32)
    {
        const int row = t >> 4;     // 0..7
        const int c4  = t & 15;
#pragma unroll
        for (int i = 0; i < 16; i++) {
            const int r = row + i * 8;
            float4 v = *(const float4*)&Qg[(size_t)(qrow0 + r) * D_MODEL + hcol + c4 * 4];
            uint4 u;
            u.x = f2tf(v.x); u.y = f2tf(v.y); u.z = f2tf(v.z); u.w = f2tf(v.w);
            *(uint4*)&Qs[r * QST + c4 * 4] = u;
        }
    }

    float o[2][8][4] = {};
    float mr[4], l[4];
#pragma unroll
    for (int i = 0; i < 4; i++) { mr[i] = -INFINITY; l[i] = 0.f; }

    for (int jb = 0; jb < S_LEN / 64; jb++) {
        __syncthreads();  // previous iter done with Ks/Vs (also orders Q on jb==0)

        const int krow0 = b * S_LEN + jb * 64;
        {
            const int row = t >> 4;
            const int c4  = t & 15;
#pragma unroll
            for (int i = 0; i < 8; i++) {
                const int r = row + i * 8;
                float4 kv = *(const float4*)&Kg[(size_t)(krow0 + r) * D_MODEL + hcol + c4 * 4];
                uint4 u;
                u.x = f2tf(kv.x); u.y = f2tf(kv.y); u.z = f2tf(kv.z); u.w = f2tf(kv.w);
                *(uint4*)&Ks[r * KST + c4 * 4] = u;
                float4 vv = *(const float4*)&Vg[(size_t)(krow0 + r) * D_MODEL + hcol + c4 * 4];
                u.x = f2tf(vv.x); u.y = f2tf(vv.y); u.z = f2tf(vv.z); u.w = f2tf(vv.w);
                *(uint4*)&Vs[r * VST + c4 * 4] = u;
            }
        }
        if (t < 64) msk[t] = mask[b * S_LEN + jb * 64 + t];
        __syncthreads();

        // ---- S = Q @ K^T  (warp: 32 q-rows x 64 k-cols) ----
        float s[2][8][4] = {};
#pragma unroll
        for (int ks = 0; ks < 8; ks++) {
            const int kc = ks * 8 + tig;
            unsigned a[2][4];
            a[0][0] = Qs[pr0 * QST + kc];
            a[0][1] = Qs[(pr0 + 8) * QST + kc];
            a[0][2] = Qs[pr0 * QST + kc + 4];
            a[0][3] = Qs[(pr0 + 8) * QST + kc + 4];
            a[1][0] = Qs[pr1 * QST + kc];
            a[1][1] = Qs[(pr1 + 8) * QST + kc];
            a[1][2] = Qs[pr1 * QST + kc + 4];
            a[1][3] = Qs[(pr1 + 8) * QST + kc + 4];
#pragma unroll
            for (int nt = 0; nt < 8; nt++) {
                unsigned b0 = Ks[(nt * 8 + g) * KST + kc];
                unsigned b1 = Ks[(nt * 8 + g) * KST + kc + 4];
                mma_tf32(s[0][nt], a[0], b0, b1);
                mma_tf32(s[1][nt], a[1], b0, b1);
            }
        }

        // ---- scale + mask + online softmax (4 row-groups per thread) ----
        float mx[4], corr[4], rs[4];
#pragma unroll
        for (int ri = 0; ri < 4; ri++) mx[ri] = -INFINITY;
#pragma unroll
        for (int nt = 0; nt < 8; nt++) {
#pragma unroll
            for (int j = 0; j < 2; j++) {
                const int mk = msk[nt * 8 + 2 * tig + j];
#pragma unroll
                for (int ri = 0; ri < 4; ri++) {
                    float v = mk ? -1e9f : s[ri >> 1][nt][(ri & 1) * 2 + j] * 0.125f;
                    s[ri >> 1][nt][(ri & 1) * 2 + j] = v;
                    mx[ri] = fmaxf(mx[ri], v);
                }
            }
        }
#pragma unroll
        for (int ri = 0; ri < 4; ri++) {
            mx[ri] = fmaxf(mx[ri], __shfl_xor_sync(0xffffffffu, mx[ri], 1));
            mx[ri] = fmaxf(mx[ri], __shfl_xor_sync(0xffffffffu, mx[ri], 2));
            const float mn = fmaxf(mr[ri], mx[ri]);
            corr[ri] = __expf(mr[ri] - mn);
            mr[ri] = mn;
            rs[ri] = 0.f;
        }
#pragma unroll
        for (int nt = 0; nt < 8; nt++) {
#pragma unroll
            for (int ri = 0; ri < 4; ri++) {
#pragma unroll
                for (int j = 0; j < 2; j++) {
                    float p = __expf(s[ri >> 1][nt][(ri & 1) * 2 + j] - mr[ri]);
                    s[ri >> 1][nt][(ri & 1) * 2 + j] = p;
                    rs[ri] += p;
                }
            }
        }
#pragma unroll
        for (int ri = 0; ri < 4; ri++) {
            rs[ri] += __shfl_xor_sync(0xffffffffu, rs[ri], 1);
            rs[ri] += __shfl_xor_sync(0xffffffffu, rs[ri], 2);
            l[ri] = l[ri] * corr[ri] + rs[ri];
        }
#pragma unroll
        for (int nt = 0; nt < 8; nt++) {
#pragma unroll
            for (int ti = 0; ti < 2; ti++) {
                o[ti][nt][0] *= corr[ti * 2];
                o[ti][nt][1] *= corr[ti * 2];
                o[ti][nt][2] *= corr[ti * 2 + 1];
                o[ti][nt][3] *= corr[ti * 2 + 1];
            }
        }

        // ---- stage P (warp-private rows), uint2 stores ----
#pragma unroll
        for (int nt = 0; nt < 8; nt++) {
            const int col = nt * 8 + 2 * tig;
            uint2 u;
            u.x = f2tf(s[0][nt][0]); u.y = f2tf(s[0][nt][1]);
            *(uint2*)&Ps[pr0 * PST + col] = u;
            u.x = f2tf(s[0][nt][2]); u.y = f2tf(s[0][nt][3]);
            *(uint2*)&Ps[(pr0 + 8) * PST + col] = u;
            u.x = f2tf(s[1][nt][0]); u.y = f2tf(s[1][nt][1]);
            *(uint2*)&Ps[pr1 * PST + col] = u;
            u.x = f2tf(s[1][nt][2]); u.y = f2tf(s[1][nt][3]);
            *(uint2*)&Ps[(pr1 + 8) * PST + col] = u;
        }
        __syncwarp();

        // ---- O += P @ V ----
#pragma unroll
        for (int ks = 0; ks < 8; ks++) {
            const int kc = ks * 8 + tig;
            unsigned a[2][4];
            a[0][0] = Ps[pr0 * PST + kc];
            a[0][1] = Ps[(pr0 + 8) * PST + kc];
            a[0][2] = Ps[pr0 * PST + kc + 4];
            a[0][3] = Ps[(pr0 + 8) * PST + kc + 4];
            a[1][0] = Ps[pr1 * PST + kc];
            a[1][1] = Ps[(pr1 + 8) * PST + kc];
            a[1][2] = Ps[pr1 * PST + kc + 4];
            a[1][3] = Ps[(pr1 + 8) * PST + kc + 4];
#pragma unroll
            for (int nt = 0; nt < 8; nt++) {
                unsigned b0 = Vs[(ks * 8 + tig) * VST + nt * 8 + g];
                unsigned b1 = Vs[(ks * 8 + tig + 4) * VST + nt * 8 + g];
                mma_tf32(o[0][nt], a[0], b0, b1);
                mma_tf32(o[1][nt], a[1], b0, b1);
            }
        }
        __syncwarp();  // P reads done before next iter's softmax rewrites it
    }

    // ---- normalize + write ----
#pragma unroll
    for (int ti = 0; ti < 2; ti++) {
        const float inv0 = 1.f / l[ti * 2];
        const float inv1 = 1.f / l[ti * 2 + 1];
        const int row0 = qrow0 + R0 + ti * 16 + g;
#pragma unroll
        for (int nt = 0; nt < 8; nt++) {
            const int col = hcol + nt * 8 + 2 * tig;
            *(float2*)&Og[(size_t)row0 * D_MODEL + col] =
                make_float2(o[ti][nt][0] * inv0, o[ti][nt][1] * inv0);
            *(float2*)&Og[(size_t)(row0 + 8) * D_MODEL + col] =
                make_float2(o[ti][nt][2] * inv1, o[ti][nt][3] * inv1);
        }
    }
}

// ---------------------------------------------------------------------------
extern "C" void kernel_launch(void* const* d_in, const int* in_sizes, int n_in,
                              void* d_out, int out_size)
{
    const float* h   = (const float*)d_in[0];
    const float* Wq  = (const float*)d_in[1];
    const float* bq  = (const float*)d_in[2];
    const float* Wk  = (const float*)d_in[3];
    const float* bk  = (const float*)d_in[4];
    const float* Wv  = (const float*)d_in[5];
    const float* bv  = (const float*)d_in[6];
    const float* Wo  = (const float*)d_in[7];
    const float* bo  = (const float*)d_in[8];
    const int*   msk = (const int*)d_in[9];
    float* out = (float*)d_out;

    void *pq, *pk, *pv, *pa;
    cudaGetSymbolAddress(&pq, g_q);
    cudaGetSymbolAddress(&pk, g_k);
    cudaGetSymbolAddress(&pv, g_v);
    cudaGetSymbolAddress(&pa, g_att);

    const int attn_smem = (128 * QST + 64 * KST + 64 * VST + 128 * PST) * 4 + 64 * 4;
    cudaFuncSetAttribute(attn_tc, cudaFuncAttributeMaxDynamicSharedMemorySize,
                         attn_smem);

    dim3 gthr(128);
    dim3 ggrid(D_MODEL / 64, ROWS / 128);   // (12, 64)

    gemm_tf32<<<ggrid, gthr>>>(h, Wq, bq, (float*)pq, ROWS, D_MODEL, D_MODEL);
    gemm_tf32<<<ggrid, gthr>>>(h, Wk, bk, (float*)pk, ROWS, D_MODEL, D_MODEL);
    gemm_tf32<<<ggrid, gthr>>>(h, Wv, bv, (float*)pv, ROWS, D_MODEL, D_MODEL);

    dim3 agrid(S_LEN / 128, BATCH * NH);    // (32, 24)
    attn_tc<<<agrid, gthr, attn_smem>>>((const float*)pq, (const float*)pk,
                                        (const float*)pv, msk, (float*)pa);

    gemm_tf32<<<ggrid, gthr>>>((const float*)pa, Wo, bo, out, ROWS, D_MODEL, D_MODEL);
}

// round 4
// speedup vs baseline: 5.9484x; 1.6240x over previous
#include <cuda_runtime.h>
#include <cuda_fp16.h>
#include <math.h>

#define S_LEN   4096
#define D_MODEL 768
#define NH      12
#define DHEAD   64
#define BATCH   2
#define ROWS    (BATCH * S_LEN)   // 8192

// Scratch (allocation-free rule: __device__ globals)
__device__ float g_q[ROWS * D_MODEL];
__device__ float g_k[ROWS * D_MODEL];
__device__ float g_v[ROWS * D_MODEL];
__device__ float g_att[ROWS * D_MODEL];

// ---------------------------------------------------------------------------
// fp16 helpers
// ---------------------------------------------------------------------------
__device__ __forceinline__ unsigned pack2(float a, float b) {
    __half2 h = __floats2half2_rn(a, b);
    return *(unsigned*)&h;
}

__device__ __forceinline__ void mma_f16(float c[4], const unsigned a[4],
                                        unsigned b0, unsigned b1) {
    asm volatile(
        "mma.sync.aligned.m16n8k16.row.col.f32.f16.f16.f32 "
        "{%0,%1,%2,%3}, {%4,%5,%6,%7}, {%8,%9}, {%0,%1,%2,%3};"
        : "+f"(c[0]), "+f"(c[1]), "+f"(c[2]), "+f"(c[3])
        : "r"(a[0]), "r"(a[1]), "r"(a[2]), "r"(a[3]), "r"(b0), "r"(b1));
}

__device__ __forceinline__ void ldsm4(unsigned r[4], const __half* p) {
    unsigned addr = (unsigned)__cvta_generic_to_shared(p);
    asm volatile("ldmatrix.sync.aligned.m8n8.x4.shared.b16 {%0,%1,%2,%3}, [%4];"
                 : "=r"(r[0]), "=r"(r[1]), "=r"(r[2]), "=r"(r[3]) : "r"(addr));
}

__device__ __forceinline__ void ldsm4t(unsigned r[4], const __half* p) {
    unsigned addr = (unsigned)__cvta_generic_to_shared(p);
    asm volatile("ldmatrix.sync.aligned.m8n8.x4.trans.shared.b16 {%0,%1,%2,%3}, [%4];"
                 : "=r"(r[0]), "=r"(r[1]), "=r"(r[2]), "=r"(r[3]) : "r"(addr));
}

// ---------------------------------------------------------------------------
// C[M,N] = A[M,K] @ W[N,K]^T + bias   (fp16 tensor cores, fp32 accum)
// Block 128x64, BK=16, 128 threads (4 warps), warp tile 32x64, double-buffered.
// Row stride 24 halves (48B): ldmatrix rows hit +12 banks/row -> conflict-free.
// ---------------------------------------------------------------------------
#define GH 24

__global__ void __launch_bounds__(128) gemm_f16(
    const float* __restrict__ A, const float* __restrict__ W,
    const float* __restrict__ bias, float* __restrict__ C,
    int M, int N, int K)
{
    __shared__ __half As[2][128 * GH];
    __shared__ __half Bs[2][64 * GH];

    const int t    = threadIdx.x;
    const int warp = t >> 5;
    const int lane = t & 31;
    const int g    = lane >> 2;
    const int tig  = lane & 3;
    const int q8   = lane >> 3;   // ldmatrix quad
    const int ri   = lane & 7;    // ldmatrix row-in-quad
    const int m0   = blockIdx.y * 128;
    const int n0   = blockIdx.x * 64;

    const int arow = t >> 2;           // 0..31
    const int ac4  = t & 3;
    const float* Ap = A + (size_t)(m0 + arow) * K + ac4 * 4;
    const float* Wp = W + (size_t)(n0 + arow) * K + ac4 * 4;

    float acc[2][8][4] = {};

    float4 ra[4], rb[2];
#pragma unroll
    for (int i = 0; i < 4; i++) ra[i] = *(const float4*)(Ap + (size_t)(32 * i) * K);
#pragma unroll
    for (int i = 0; i < 2; i++) rb[i] = *(const float4*)(Wp + (size_t)(32 * i) * K);

    int buf = 0;
    for (int k0 = 0; k0 < K; k0 += 16) {
#pragma unroll
        for (int i = 0; i < 4; i++) {
            uint2 u = make_uint2(pack2(ra[i].x, ra[i].y), pack2(ra[i].z, ra[i].w));
            *(uint2*)&As[buf][(arow + 32 * i) * GH + ac4 * 4] = u;
        }
#pragma unroll
        for (int i = 0; i < 2; i++) {
            uint2 u = make_uint2(pack2(rb[i].x, rb[i].y), pack2(rb[i].z, rb[i].w));
            *(uint2*)&Bs[buf][(arow + 32 * i) * GH + ac4 * 4] = u;
        }
        __syncthreads();

        if (k0 + 16 < K) {
#pragma unroll
            for (int i = 0; i < 4; i++)
                ra[i] = *(const float4*)(Ap + (size_t)(32 * i) * K + k0 + 16);
#pragma unroll
            for (int i = 0; i < 2; i++)
                rb[i] = *(const float4*)(Wp + (size_t)(32 * i) * K + k0 + 16);
        }

        unsigned a[2][4];
#pragma unroll
        for (int ti = 0; ti < 2; ti++)
            ldsm4(a[ti], &As[buf][(warp * 32 + ti * 16 + (q8 & 1) * 8 + ri) * GH
                                  + (q8 >> 1) * 8]);
#pragma unroll
        for (int nt = 0; nt < 8; nt += 2) {
            unsigned b[4];
            ldsm4(b, &Bs[buf][((nt + (q8 >> 1)) * 8 + ri) * GH + (q8 & 1) * 8]);
            mma_f16(acc[0][nt],     a[0], b[0], b[1]);
            mma_f16(acc[1][nt],     a[1], b[0], b[1]);
            mma_f16(acc[0][nt + 1], a[0], b[2], b[3]);
            mma_f16(acc[1][nt + 1], a[1], b[2], b[3]);
        }
        buf ^= 1;   // stores go to the other buffer next iter; one sync per tile
    }

#pragma unroll
    for (int ti = 0; ti < 2; ti++) {
        const int row0 = m0 + warp * 32 + ti * 16 + g;
#pragma unroll
        for (int nt = 0; nt < 8; nt++) {
            const int col = n0 + nt * 8 + 2 * tig;
            const float b0v = bias[col], b1v = bias[col + 1];
            *(float2*)&C[(size_t)row0 * N + col] =
                make_float2(acc[ti][nt][0] + b0v, acc[ti][nt][1] + b1v);
            *(float2*)&C[(size_t)(row0 + 8) * N + col] =
                make_float2(acc[ti][nt][2] + b0v, acc[ti][nt][3] + b1v);
        }
    }
}

// ---------------------------------------------------------------------------
// Flash attention, fp16 tensor cores + ldmatrix.
// Grid: (S/128, B*H). Block 128 threads (4 warps); warp w owns q-rows [32w,32w+32).
// smem halves, stride 72 (144B rows -> ldmatrix conflict-free).
// ---------------------------------------------------------------------------
#define HST 72

__global__ void __launch_bounds__(128) attn_tc(
    const float* __restrict__ Qg, const float* __restrict__ Kg,
    const float* __restrict__ Vg, const int* __restrict__ mask,
    float* __restrict__ Og)
{
    extern __shared__ __half sh[];
    __half* Qh = sh;                     // 128*72
    __half* Kh = Qh + 128 * HST;         // 64*72
    __half* Vh = Kh + 64 * HST;          // 64*72
    __half* Ph = Vh + 64 * HST;          // 128*72
    int* msk = (int*)(Ph + 128 * HST);   // 64

    const int t    = threadIdx.x;
    const int warp = t >> 5;
    const int lane = t & 31;
    const int g    = lane >> 2;
    const int tig  = lane & 3;
    const int q8   = lane >> 3;
    const int ri   = lane & 7;

    const int qb = blockIdx.x;
    const int bh = blockIdx.y;
    const int b  = bh / NH;
    const int hh = bh % NH;
    const int qrow0 = b * S_LEN + qb * 128;
    const int hcol  = hh * DHEAD;

    const int R0 = warp * 32;

    // Load Q tile 128x64 -> half
    {
        const int row = t >> 4;     // 0..7
        const int c4  = t & 15;
#pragma unroll
        for (int i = 0; i < 16; i++) {
            const int r = row + i * 8;
            float4 v = *(const float4*)&Qg[(size_t)(qrow0 + r) * D_MODEL + hcol + c4 * 4];
            uint2 u = make_uint2(pack2(v.x, v.y), pack2(v.z, v.w));
            *(uint2*)&Qh[r * HST + c4 * 4] = u;
        }
    }

    float o[2][8][4] = {};
    float mr[4], l[4];
#pragma unroll
    for (int i = 0; i < 4; i++) { mr[i] = -INFINITY; l[i] = 0.f; }

    for (int jb = 0; jb < S_LEN / 64; jb++) {
        __syncthreads();  // previous iter done with Kh/Vh (also orders Q on jb==0)

        const int krow0 = b * S_LEN + jb * 64;
        {
            const int row = t >> 4;
            const int c4  = t & 15;
#pragma unroll
            for (int i = 0; i < 8; i++) {
                const int r = row + i * 8;
                float4 kv = *(const float4*)&Kg[(size_t)(krow0 + r) * D_MODEL + hcol + c4 * 4];
                *(uint2*)&Kh[r * HST + c4 * 4] =
                    make_uint2(pack2(kv.x, kv.y), pack2(kv.z, kv.w));
                float4 vv = *(const float4*)&Vg[(size_t)(krow0 + r) * D_MODEL + hcol + c4 * 4];
                *(uint2*)&Vh[r * HST + c4 * 4] =
                    make_uint2(pack2(vv.x, vv.y), pack2(vv.z, vv.w));
            }
        }
        if (t < 64) msk[t] = mask[b * S_LEN + jb * 64 + t];
        __syncthreads();

        // ---- S = Q @ K^T  (warp: 32 q-rows x 64 keys, k = 64 d) ----
        float s[2][8][4] = {};
#pragma unroll
        for (int kc = 0; kc < 4; kc++) {
            unsigned a[2][4];
#pragma unroll
            for (int ti = 0; ti < 2; ti++)
                ldsm4(a[ti], &Qh[(R0 + ti * 16 + (q8 & 1) * 8 + ri) * HST
                                 + kc * 16 + (q8 >> 1) * 8]);
#pragma unroll
            for (int nt = 0; nt < 8; nt += 2) {
                unsigned bb[4];
                ldsm4(bb, &Kh[((nt + (q8 >> 1)) * 8 + ri) * HST + kc * 16 + (q8 & 1) * 8]);
                mma_f16(s[0][nt],     a[0], bb[0], bb[1]);
                mma_f16(s[1][nt],     a[1], bb[0], bb[1]);
                mma_f16(s[0][nt + 1], a[0], bb[2], bb[3]);
                mma_f16(s[1][nt + 1], a[1], bb[2], bb[3]);
            }
        }

        // ---- scale + mask + online softmax ----
        float mx[4], corr[4], rs[4];
#pragma unroll
        for (int ri2 = 0; ri2 < 4; ri2++) mx[ri2] = -INFINITY;
#pragma unroll
        for (int nt = 0; nt < 8; nt++) {
#pragma unroll
            for (int j = 0; j < 2; j++) {
                const int mk = msk[nt * 8 + 2 * tig + j];
#pragma unroll
                for (int ri2 = 0; ri2 < 4; ri2++) {
                    float v = mk ? -1e9f : s[ri2 >> 1][nt][(ri2 & 1) * 2 + j] * 0.125f;
                    s[ri2 >> 1][nt][(ri2 & 1) * 2 + j] = v;
                    mx[ri2] = fmaxf(mx[ri2], v);
                }
            }
        }
#pragma unroll
        for (int ri2 = 0; ri2 < 4; ri2++) {
            mx[ri2] = fmaxf(mx[ri2], __shfl_xor_sync(0xffffffffu, mx[ri2], 1));
            mx[ri2] = fmaxf(mx[ri2], __shfl_xor_sync(0xffffffffu, mx[ri2], 2));
            const float mn = fmaxf(mr[ri2], mx[ri2]);
            corr[ri2] = __expf(mr[ri2] - mn);
            mr[ri2] = mn;
            rs[ri2] = 0.f;
        }
#pragma unroll
        for (int nt = 0; nt < 8; nt++) {
#pragma unroll
            for (int ri2 = 0; ri2 < 4; ri2++) {
#pragma unroll
                for (int j = 0; j < 2; j++) {
                    float p = __expf(s[ri2 >> 1][nt][(ri2 & 1) * 2 + j] - mr[ri2]);
                    s[ri2 >> 1][nt][(ri2 & 1) * 2 + j] = p;
                    rs[ri2] += p;
                }
            }
        }
#pragma unroll
        for (int ri2 = 0; ri2 < 4; ri2++) {
            rs[ri2] += __shfl_xor_sync(0xffffffffu, rs[ri2], 1);
            rs[ri2] += __shfl_xor_sync(0xffffffffu, rs[ri2], 2);
            l[ri2] = l[ri2] * corr[ri2] + rs[ri2];
        }
#pragma unroll
        for (int nt = 0; nt < 8; nt++) {
#pragma unroll
            for (int ti = 0; ti < 2; ti++) {
                o[ti][nt][0] *= corr[ti * 2];
                o[ti][nt][1] *= corr[ti * 2];
                o[ti][nt][2] *= corr[ti * 2 + 1];
                o[ti][nt][3] *= corr[ti * 2 + 1];
            }
        }

        // ---- stage P (warp-private rows) as half ----
#pragma unroll
        for (int nt = 0; nt < 8; nt++) {
            const int col = nt * 8 + 2 * tig;
#pragma unroll
            for (int ti = 0; ti < 2; ti++) {
                *(unsigned*)&Ph[(R0 + ti * 16 + g) * HST + col] =
                    pack2(s[ti][nt][0], s[ti][nt][1]);
                *(unsigned*)&Ph[(R0 + ti * 16 + 8 + g) * HST + col] =
                    pack2(s[ti][nt][2], s[ti][nt][3]);
            }
        }
        __syncwarp();

        // ---- O += P @ V  (k = 64 keys, n = 64 dh; V via ldmatrix.trans) ----
#pragma unroll
        for (int kc = 0; kc < 4; kc++) {
            unsigned a[2][4];
#pragma unroll
            for (int ti = 0; ti < 2; ti++)
                ldsm4(a[ti], &Ph[(R0 + ti * 16 + (q8 & 1) * 8 + ri) * HST
                                 + kc * 16 + (q8 >> 1) * 8]);
#pragma unroll
            for (int nt = 0; nt < 8; nt += 2) {
                unsigned bb[4];
                ldsm4t(bb, &Vh[(kc * 16 + (q8 & 1) * 8 + ri) * HST + (nt + (q8 >> 1)) * 8]);
                mma_f16(o[0][nt],     a[0], bb[0], bb[1]);
                mma_f16(o[1][nt],     a[1], bb[0], bb[1]);
                mma_f16(o[0][nt + 1], a[0], bb[2], bb[3]);
                mma_f16(o[1][nt + 1], a[1], bb[2], bb[3]);
            }
        }
        __syncwarp();  // P reads done before next iter's softmax rewrites it
    }

    // ---- normalize + write ----
#pragma unroll
    for (int ti = 0; ti < 2; ti++) {
        const float inv0 = 1.f / l[ti * 2];
        const float inv1 = 1.f / l[ti * 2 + 1];
        const int row0 = qrow0 + R0 + ti * 16 + g;
#pragma unroll
        for (int nt = 0; nt < 8; nt++) {
            const int col = hcol + nt * 8 + 2 * tig;
            *(float2*)&Og[(size_t)row0 * D_MODEL + col] =
                make_float2(o[ti][nt][0] * inv0, o[ti][nt][1] * inv0);
            *(float2*)&Og[(size_t)(row0 + 8) * D_MODEL + col] =
                make_float2(o[ti][nt][2] * inv1, o[ti][nt][3] * inv1);
        }
    }
}

// ---------------------------------------------------------------------------
extern "C" void kernel_launch(void* const* d_in, const int* in_sizes, int n_in,
                              void* d_out, int out_size)
{
    const float* h   = (const float*)d_in[0];
    const float* Wq  = (const float*)d_in[1];
    const float* bq  = (const float*)d_in[2];
    const float* Wk  = (const float*)d_in[3];
    const float* bk  = (const float*)d_in[4];
    const float* Wv  = (const float*)d_in[5];
    const float* bv  = (const float*)d_in[6];
    const float* Wo  = (const float*)d_in[7];
    const float* bo  = (const float*)d_in[8];
    const int*   msk = (const int*)d_in[9];
    float* out = (float*)d_out;

    void *pq, *pk, *pv, *pa;
    cudaGetSymbolAddress(&pq, g_q);
    cudaGetSymbolAddress(&pk, g_k);
    cudaGetSymbolAddress(&pv, g_v);
    cudaGetSymbolAddress(&pa, g_att);

    const int attn_smem = (128 * HST + 64 * HST + 64 * HST + 128 * HST) * 2 + 64 * 4;
    cudaFuncSetAttribute(attn_tc, cudaFuncAttributeMaxDynamicSharedMemorySize,
                         attn_smem);

    dim3 gthr(128);
    dim3 ggrid(D_MODEL / 64, ROWS / 128);   // (12, 64)

    gemm_f16<<<ggrid, gthr>>>(h, Wq, bq, (float*)pq, ROWS, D_MODEL, D_MODEL);
    gemm_f16<<<ggrid, gthr>>>(h, Wk, bk, (float*)pk, ROWS, D_MODEL, D_MODEL);
    gemm_f16<<<ggrid, gthr>>>(h, Wv, bv, (float*)pv, ROWS, D_MODEL, D_MODEL);

    dim3 agrid(S_LEN / 128, BATCH * NH);    // (32, 24)
    attn_tc<<<agrid, gthr, attn_smem>>>((const float*)pq, (const float*)pk,
                                        (const float*)pv, msk, (float*)pa);

    gemm_f16<<<ggrid, gthr>>>((const float*)pa, Wo, bo, out, ROWS, D_MODEL, D_MODEL);
}